// round 16
// baseline (speedup 1.0000x reference)
#include <cuda_runtime.h>
#include <cuda_fp16.h>

// QConv2d: 3x3 conv, B=16, C=32, N=64, H=W=56, stride 1, pad 1.
// Exact per-k fp16 (E5M10) requantized accumulation (bit-identical path):
//   p   = fp16(fp32(a * w))  -> FMUL.rn + cvt.rn.f16x2.f32 (packs 2 n-lanes)
//   acc = fp16(acc + p)      -> HADD2
// k order = c*9 + i*3 + j, matching lax.scan order.
//
// R16 = R15 with the prefetch-tail OOB fixed: the last iteration prefetches
// nci=96 which reads up to ~192B past the weight array; smem now carries a
// 256B pad so that dead read stays inside our allocation (values unused).

#define TB 224

#define ROWP 60
#define SIN_FLOATS (6 * 32 * ROWP)           // 11520 : [rabs(6)][c(32)][60]
#define SW_FLOATS  (96 * 48)                 // 4608  : [ci(96)][48 floats]
#define SMEM_BYTES ((SIN_FLOATS + SW_FLOATS) * 4 + 256)  // 64768 -> 3 CTAs/SM

__device__ __forceinline__ __half2 cvt_pair(float n0, float n1) {
    unsigned h;
    // cvt.rn.f16x2.f32 d, a, b : a -> upper half, b -> lower half
    asm("cvt.rn.f16x2.f32 %0, %1, %2;" : "=r"(h) : "f"(n1), "f"(n0));
    return *reinterpret_cast<__half2*>(&h);
}

__global__ void __launch_bounds__(TB, 3) qconv2d_kernel(
    const float* __restrict__ x,      // [16][32][56][56]
    const float* __restrict__ w,      // [64][32][3][3] = [64][288]
    const float* __restrict__ bias,   // [64]
    float* __restrict__ out)          // [16][64][56][56]
{
    extern __shared__ float sm[];
    float* sin = sm;                  // [rabs][c][60]
    float* sw  = sm + SIN_FLOATS;     // [ci][np: 16B j01][np: 8B j2]

    const int yq  = blockIdx.x;       // row quad 0..13 -> rows 4*yq .. 4*yq+3
    const int b   = blockIdx.y;       // batch 0..15
    const int nq  = blockIdx.z;       // n quarter 0..3 -> n = 16*nq .. +15
    const int tid = threadIdx.x;
    const int y0  = 4 * yq;

    // ---- weights: quantize (fp16 value in fp32), repack per (ci, np) ----
    // layout per ci (48 floats): [np(8) x {w0x,w0y,w1x,w1y}][np(8) x {w2x,w2y}]
    for (int idx = tid; idx < 16 * 288; idx += TB) {
        int nc = idx / 288;
        int k  = idx % 288;           // coalesced over k
        int ci = k / 3;
        int j  = k % 3;
        int np = nc >> 1;
        int l  = nc & 1;
        int off = (j < 2) ? (np * 4 + j * 2 + l) : (32 + np * 2 + l);
        sw[ci * 48 + off] = __half2float(__float2half_rn(w[(nq * 16 + nc) * 288 + k]));
    }

    // ---- input rows y0-1..y0+4, layout [rabs][c][60] (x offset by 1) ----
    const float* xb = x + (size_t)b * 32 * 56 * 56;
    for (int idx = tid; idx < SIN_FLOATS; idx += TB) {
        int rabs = idx / (32 * ROWP);
        int rem  = idx % (32 * ROWP);
        int c    = rem / ROWP;
        int xs   = rem % ROWP;
        int yg   = y0 - 1 + rabs;
        int xg   = xs - 1;
        float v = 0.0f;
        if (yg >= 0 && yg < 56 && xg >= 0 && xg < 56)
            v = xb[(c * 56 + yg) * 56 + xg];
        sin[idx] = v;
    }
    __syncthreads();

    const int lane = tid & 31;
    const int wrp  = tid >> 5;            // 0..6
    const int np   = lane & 7;            // n-pair within quarter (0..7)
    const int h    = lane >> 3;           // px group slot 0..3
    const int grp  = wrp * 4 + h;         // 0..27
    const int row  = grp / 7;             // 0..3 (output row within quad)
    const int x0   = (grp % 7) * 8;       // output x base, 8 px per thread

    __half2 acc0 = __float2half2_rn(0.0f);
    __half2 acc1 = acc0, acc2 = acc0, acc3 = acc0;
    __half2 acc4 = acc0, acc5 = acc0, acc6 = acc0, acc7 = acc0;

    const float* tb  = sin + row * (32 * ROWP) + x0;   // (c,i): + i*1920 + c*60
    const float* wb  = sw + np * 4;                    // + ci*48
    const float* wb2 = sw + 32 + np * 2;               // + ci*48

    // prefetch (c=0, i=0)
    float4 A   = *reinterpret_cast<const float4*>(tb);
    float4 Bv  = *reinterpret_cast<const float4*>(tb + 4);
    float2 Cv  = *reinterpret_cast<const float2*>(tb + 8);
    float4 W01 = *reinterpret_cast<const float4*>(wb);
    float2 W2  = *reinterpret_cast<const float2*>(wb2);

    #pragma unroll 2
    for (int c = 0; c < 32; ++c) {
        #pragma unroll
        for (int i = 0; i < 3; ++i) {
            // ---- prefetch next (c,i); final overshoot lands in the 256B pad ----
            const float* na = (i < 2) ? (tb + (i + 1) * (32 * ROWP) + c * ROWP)
                                      : (tb + (c + 1) * ROWP);
            const int nci = c * 3 + i + 1;
            float4 nA   = *reinterpret_cast<const float4*>(na);
            float4 nB   = *reinterpret_cast<const float4*>(na + 4);
            float2 nC   = *reinterpret_cast<const float2*>(na + 8);
            float4 nW01 = *reinterpret_cast<const float4*>(wb + nci * 48);
            float2 nW2  = *reinterpret_cast<const float2*>(wb2 + nci * 48);

            // ---- compute current (c,i): j = 0,1,2 in k order ----
            const float w0x = W01.x, w0y = W01.y, w1x = W01.z, w1y = W01.w;
            const float w2x = W2.x,  w2y = W2.y;

            // j = 0 : px p uses a_p
            acc0 = __hadd2(acc0, cvt_pair(A.x * w0x, A.x * w0y));
            acc1 = __hadd2(acc1, cvt_pair(A.y * w0x, A.y * w0y));
            acc2 = __hadd2(acc2, cvt_pair(A.z * w0x, A.z * w0y));
            acc3 = __hadd2(acc3, cvt_pair(A.w * w0x, A.w * w0y));
            acc4 = __hadd2(acc4, cvt_pair(Bv.x * w0x, Bv.x * w0y));
            acc5 = __hadd2(acc5, cvt_pair(Bv.y * w0x, Bv.y * w0y));
            acc6 = __hadd2(acc6, cvt_pair(Bv.z * w0x, Bv.z * w0y));
            acc7 = __hadd2(acc7, cvt_pair(Bv.w * w0x, Bv.w * w0y));
            // j = 1 : px p uses a_{p+1}
            acc0 = __hadd2(acc0, cvt_pair(A.y * w1x, A.y * w1y));
            acc1 = __hadd2(acc1, cvt_pair(A.z * w1x, A.z * w1y));
            acc2 = __hadd2(acc2, cvt_pair(A.w * w1x, A.w * w1y));
            acc3 = __hadd2(acc3, cvt_pair(Bv.x * w1x, Bv.x * w1y));
            acc4 = __hadd2(acc4, cvt_pair(Bv.y * w1x, Bv.y * w1y));
            acc5 = __hadd2(acc5, cvt_pair(Bv.z * w1x, Bv.z * w1y));
            acc6 = __hadd2(acc6, cvt_pair(Bv.w * w1x, Bv.w * w1y));
            acc7 = __hadd2(acc7, cvt_pair(Cv.x * w1x, Cv.x * w1y));
            // j = 2 : px p uses a_{p+2}
            acc0 = __hadd2(acc0, cvt_pair(A.z * w2x, A.z * w2y));
            acc1 = __hadd2(acc1, cvt_pair(A.w * w2x, A.w * w2y));
            acc2 = __hadd2(acc2, cvt_pair(Bv.x * w2x, Bv.x * w2y));
            acc3 = __hadd2(acc3, cvt_pair(Bv.y * w2x, Bv.y * w2y));
            acc4 = __hadd2(acc4, cvt_pair(Bv.z * w2x, Bv.z * w2y));
            acc5 = __hadd2(acc5, cvt_pair(Bv.w * w2x, Bv.w * w2y));
            acc6 = __hadd2(acc6, cvt_pair(Cv.x * w2x, Cv.x * w2y));
            acc7 = __hadd2(acc7, cvt_pair(Cv.y * w2x, Cv.y * w2y));

            // rotate buffers
            A = nA; Bv = nB; Cv = nC; W01 = nW01; W2 = nW2;
        }
    }

    // ---- epilogue: out = fp32(fp16(acc + fp16(bias))) ----
    const int n0 = nq * 16 + 2 * np;
    __half2 qb = __halves2half2(__float2half_rn(bias[n0]),
                                __float2half_rn(bias[n0 + 1]));

    __half2 r0 = __hadd2(acc0, qb), r1 = __hadd2(acc1, qb);
    __half2 r2 = __hadd2(acc2, qb), r3 = __hadd2(acc3, qb);
    __half2 r4 = __hadd2(acc4, qb), r5 = __hadd2(acc5, qb);
    __half2 r6 = __hadd2(acc6, qb), r7 = __hadd2(acc7, qb);

    const int y = y0 + row;
    size_t o0 = (((size_t)b * 64 + n0) * 56 + y) * 56 + x0;
    size_t o1 = (((size_t)b * 64 + n0 + 1) * 56 + y) * 56 + x0;

    *reinterpret_cast<float4*>(out + o0) =
        make_float4(__low2float(r0), __low2float(r1), __low2float(r2), __low2float(r3));
    *reinterpret_cast<float4*>(out + o0 + 4) =
        make_float4(__low2float(r4), __low2float(r5), __low2float(r6), __low2float(r7));
    *reinterpret_cast<float4*>(out + o1) =
        make_float4(__high2float(r0), __high2float(r1), __high2float(r2), __high2float(r3));
    *reinterpret_cast<float4*>(out + o1 + 4) =
        make_float4(__high2float(r4), __high2float(r5), __high2float(r6), __high2float(r7));
}

extern "C" void kernel_launch(void* const* d_in, const int* in_sizes, int n_in,
                              void* d_out, int out_size)
{
    const float* x    = (const float*)d_in[0];
    const float* w    = (const float*)d_in[1];
    const float* bias = (const float*)d_in[2];
    float* out = (float*)d_out;

    cudaFuncSetAttribute(qconv2d_kernel,
                         cudaFuncAttributeMaxDynamicSharedMemorySize,
                         SMEM_BYTES);

    dim3 grid(14, 16, 4);   // (row quad, batch, n quarter)
    qconv2d_kernel<<<grid, TB, SMEM_BYTES>>>(x, w, bias, out);
}

// round 17
// speedup vs baseline: 1.0507x; 1.0507x over previous
#include <cuda_runtime.h>
#include <cuda_fp16.h>

// QConv2d: 3x3 conv, B=16, C=32, N=64, H=W=56, stride 1, pad 1.
// Exact per-k fp16 (E5M10) requantized accumulation (bit-identical path):
//   p   = fp16(fp32(a * w))  -> FMUL.rn + cvt.rn.f16x2.f32 (packs 2 n-lanes)
//   acc = fp16(acc + p)      -> HADD2
// k order = c*9 + i*3 + j, matching lax.scan order.
//
// R17: 42 warps + single-wave depth. Tile = 4 rows x 32 n, TB=448; weights
// packed fp16 (exact H2F re-expansion) so smem = 70656B -> 3 CTAs/SM,
// conc 444, grid 448 -> depth 1.009 (one near-perfect wave; 4 stragglers
// run solo with 14 warps each). Inner loop = R8's 8px/thread, 8 chains.

#define TB 448

#define ROWP 60                            // padded input row (floats)
#define NROWS 6                            // 4 output rows + halo
#define SIN_FLOATS (32 * NROWS * ROWP)     // 11520 -> 46080 B
#define SW_HALVES  (96 * 16 * 8)           // [(ci)][np(16)][8 halves] -> 24576 B
#define SMEM_BYTES (SIN_FLOATS * 4 + SW_HALVES * 2)   // 70656 -> 3 CTAs/SM

__device__ __forceinline__ __half2 cvt_pair(float n0, float n1) {
    unsigned h;
    // cvt.rn.f16x2.f32 d, a, b : a -> upper half, b -> lower half
    asm("cvt.rn.f16x2.f32 %0, %1, %2;" : "=r"(h) : "f"(n1), "f"(n0));
    return *reinterpret_cast<__half2*>(&h);
}

__global__ void __launch_bounds__(TB, 3) qconv2d_kernel(
    const float* __restrict__ x,      // [16][32][56][56]
    const float* __restrict__ w,      // [64][32][3][3] = [64][288]
    const float* __restrict__ bias,   // [64]
    float* __restrict__ out)          // [16][64][56][56]
{
    extern __shared__ float sm[];
    float*  sin = sm;                                  // [c][r(6)][ROWP]
    __half* swh = reinterpret_cast<__half*>(sm + SIN_FLOATS);  // packed weights

    const int yq  = blockIdx.x;       // row quad 0..13 -> rows 4*yq .. 4*yq+3
    const int b   = blockIdx.y;       // batch 0..15
    const int nh  = blockIdx.z;       // n half 0..1 -> n = 32*nh .. 32*nh+31
    const int tid = threadIdx.x;
    const int y0  = 4 * yq;

    // ---- weights: quantize to fp16, pack [ci][np(16)][j*2+l] (16B records) ----
    for (int idx = tid; idx < 32 * 288; idx += TB) {
        int nc = idx / 288;
        int k  = idx % 288;           // coalesced over k
        int ci = k / 3;               // c*3 + i
        int j  = k % 3;
        int np = nc >> 1;
        int l  = nc & 1;
        swh[(ci * 16 + np) * 8 + j * 2 + l] =
            __float2half_rn(w[(nh * 32 + nc) * 288 + k]);
    }

    // ---- input rows y0-1..y0+4, 32 ch, padded rows of 60 (x offset by 1) ----
    const float* xb = x + (size_t)b * 32 * 56 * 56;
    for (int idx = tid; idx < SIN_FLOATS; idx += TB) {
        int c   = idx / (NROWS * ROWP);
        int rr  = idx % (NROWS * ROWP);
        int r   = rr / ROWP;
        int xs  = rr % ROWP;
        int yg  = y0 - 1 + r;
        int xg  = xs - 1;
        float v = 0.0f;
        if (yg >= 0 && yg < 56 && xg >= 0 && xg < 56)
            v = xb[(c * 56 + yg) * 56 + xg];
        sin[idx] = v;
    }
    __syncthreads();

    const int lane = tid & 31;
    const int wrp  = tid >> 5;            // 0..13
    const int np   = lane & 15;           // n-pair within half (0..15)
    const int h    = lane >> 4;           // px group slot 0/1
    const int grp  = wrp * 2 + h;         // 0..27
    const int row  = grp / 7;             // 0..3 (output row within quad)
    const int x0   = (grp % 7) * 8;       // output x base, 8 px per thread

    __half2 acc0 = __float2half2_rn(0.0f);
    __half2 acc1 = acc0, acc2 = acc0, acc3 = acc0;
    __half2 acc4 = acc0, acc5 = acc0, acc6 = acc0, acc7 = acc0;

    const __half* swt = swh + np * 8;            // +ci*128 halves per (c,i)
    const float*  ab  = sin + row * ROWP + x0;   // 16B aligned

    #pragma unroll 2
    for (int c = 0; c < 32; ++c) {
        #pragma unroll
        for (int i = 0; i < 3; ++i) {
            const float* ar = ab + (c * NROWS + i) * ROWP;
            const float4 A = *reinterpret_cast<const float4*>(ar);       // a0..a3
            const float4 B = *reinterpret_cast<const float4*>(ar + 4);   // a4..a7
            const float2 C = *reinterpret_cast<const float2*>(ar + 8);   // a8,a9

            // one LDS.128 per (c,i): three fp16 j-pairs; exact H2F expansion
            uint4 wb = *reinterpret_cast<const uint4*>(swt + (c * 3 + i) * 128);
            const float2 w0 = __half22float2(*reinterpret_cast<__half2*>(&wb.x));
            const float2 w1 = __half22float2(*reinterpret_cast<__half2*>(&wb.y));
            const float2 w2 = __half22float2(*reinterpret_cast<__half2*>(&wb.z));

            // j = 0 : px p uses a_p
            acc0 = __hadd2(acc0, cvt_pair(A.x * w0.x, A.x * w0.y));
            acc1 = __hadd2(acc1, cvt_pair(A.y * w0.x, A.y * w0.y));
            acc2 = __hadd2(acc2, cvt_pair(A.z * w0.x, A.z * w0.y));
            acc3 = __hadd2(acc3, cvt_pair(A.w * w0.x, A.w * w0.y));
            acc4 = __hadd2(acc4, cvt_pair(B.x * w0.x, B.x * w0.y));
            acc5 = __hadd2(acc5, cvt_pair(B.y * w0.x, B.y * w0.y));
            acc6 = __hadd2(acc6, cvt_pair(B.z * w0.x, B.z * w0.y));
            acc7 = __hadd2(acc7, cvt_pair(B.w * w0.x, B.w * w0.y));
            // j = 1 : px p uses a_{p+1}
            acc0 = __hadd2(acc0, cvt_pair(A.y * w1.x, A.y * w1.y));
            acc1 = __hadd2(acc1, cvt_pair(A.z * w1.x, A.z * w1.y));
            acc2 = __hadd2(acc2, cvt_pair(A.w * w1.x, A.w * w1.y));
            acc3 = __hadd2(acc3, cvt_pair(B.x * w1.x, B.x * w1.y));
            acc4 = __hadd2(acc4, cvt_pair(B.y * w1.x, B.y * w1.y));
            acc5 = __hadd2(acc5, cvt_pair(B.z * w1.x, B.z * w1.y));
            acc6 = __hadd2(acc6, cvt_pair(B.w * w1.x, B.w * w1.y));
            acc7 = __hadd2(acc7, cvt_pair(C.x * w1.x, C.x * w1.y));
            // j = 2 : px p uses a_{p+2}
            acc0 = __hadd2(acc0, cvt_pair(A.z * w2.x, A.z * w2.y));
            acc1 = __hadd2(acc1, cvt_pair(A.w * w2.x, A.w * w2.y));
            acc2 = __hadd2(acc2, cvt_pair(B.x * w2.x, B.x * w2.y));
            acc3 = __hadd2(acc3, cvt_pair(B.y * w2.x, B.y * w2.y));
            acc4 = __hadd2(acc4, cvt_pair(B.z * w2.x, B.z * w2.y));
            acc5 = __hadd2(acc5, cvt_pair(B.w * w2.x, B.w * w2.y));
            acc6 = __hadd2(acc6, cvt_pair(C.x * w2.x, C.x * w2.y));
            acc7 = __hadd2(acc7, cvt_pair(C.y * w2.x, C.y * w2.y));
        }
    }

    // ---- epilogue: out = fp32(fp16(acc + fp16(bias))) ----
    const int n0 = nh * 32 + 2 * np;
    __half2 qb = __halves2half2(__float2half_rn(bias[n0]),
                                __float2half_rn(bias[n0 + 1]));

    __half2 r0 = __hadd2(acc0, qb), r1 = __hadd2(acc1, qb);
    __half2 r2 = __hadd2(acc2, qb), r3 = __hadd2(acc3, qb);
    __half2 r4 = __hadd2(acc4, qb), r5 = __hadd2(acc5, qb);
    __half2 r6 = __hadd2(acc6, qb), r7 = __hadd2(acc7, qb);

    const int y = y0 + row;
    size_t o0 = (((size_t)b * 64 + n0) * 56 + y) * 56 + x0;
    size_t o1 = (((size_t)b * 64 + n0 + 1) * 56 + y) * 56 + x0;

    *reinterpret_cast<float4*>(out + o0) =
        make_float4(__low2float(r0), __low2float(r1), __low2float(r2), __low2float(r3));
    *reinterpret_cast<float4*>(out + o0 + 4) =
        make_float4(__low2float(r4), __low2float(r5), __low2float(r6), __low2float(r7));
    *reinterpret_cast<float4*>(out + o1) =
        make_float4(__high2float(r0), __high2float(r1), __high2float(r2), __high2float(r3));
    *reinterpret_cast<float4*>(out + o1 + 4) =
        make_float4(__high2float(r4), __high2float(r5), __high2float(r6), __high2float(r7));
}

extern "C" void kernel_launch(void* const* d_in, const int* in_sizes, int n_in,
                              void* d_out, int out_size)
{
    const float* x    = (const float*)d_in[0];
    const float* w    = (const float*)d_in[1];
    const float* bias = (const float*)d_in[2];
    float* out = (float*)d_out;

    cudaFuncSetAttribute(qconv2d_kernel,
                         cudaFuncAttributeMaxDynamicSharedMemorySize,
                         SMEM_BYTES);

    dim3 grid(14, 16, 2);   // (row quad, batch, n half) = 448 CTAs
    qconv2d_kernel<<<grid, TB, SMEM_BYTES>>>(x, w, bias, out);
}